// round 4
// baseline (speedup 1.0000x reference)
#include <cuda_runtime.h>
#include <cuda_fp16.h>
#include <cstdint>
#include <math.h>

#define BATCH 512
#define NSEQ  128
#define DDIM  128
#define GAMMA_F 0.001f
#define BIGF 1e30f

#define NDIAG 255          // 2*NSEQ-1
#define P     132          // smem pitch (floats) for X/Y staging
#define DP_H  130          // diag-buffer pitch in halves (65 words)

// Scratch: diag-major fp16 cost matrix, per batch dense [255][128]
__device__ __half g_Dh[(size_t)BATCH * NDIAG * NSEQ];
__device__ float  g_dtw[BATCH];

__device__ __forceinline__ uint32_t f2tf32(float v) {
    uint32_t r;
    asm("cvt.rna.tf32.f32 %0, %1;" : "=r"(r) : "f"(v));
    return r;
}
__device__ __forceinline__ void mma_tf32(float c[4], const uint32_t a[4],
                                         const uint32_t b[2]) {
    asm volatile(
        "mma.sync.aligned.m16n8k8.row.col.f32.tf32.tf32.f32 "
        "{%0,%1,%2,%3}, {%4,%5,%6,%7}, {%8,%9}, {%0,%1,%2,%3};\n"
        : "+f"(c[0]), "+f"(c[1]), "+f"(c[2]), "+f"(c[3])
        : "r"(a[0]), "r"(a[1]), "r"(a[2]), "r"(a[3]), "r"(b[0]), "r"(b[1]));
}

// ============================================================================
// Kernel A: per batch b, xy-gram via HMMA tf32; D = xx + yy - 2*xy written
// fp16, DIAG-MAJOR (g_Dh[b][k=i+j][j]) via a padded smem scatter.
// 256 threads = 8 warps in a 2(m) x 4(n) grid; warp tile 64x32 (4x4 MMA tiles).
// ============================================================================
#define SM_DYN_BYTES (2 * NSEQ * P * 4 + NDIAG * DP_H * 2 + 16)

__global__ __launch_bounds__(256) void mma_cost_kernel(const float* __restrict__ X,
                                                       const float* __restrict__ Y) {
    extern __shared__ float sm[];
    float* Xs = sm;                         // [128][132]
    float* Ys = sm + NSEQ * P;              // [128][132]
    __half* Dd = (__half*)(sm + 2 * NSEQ * P);  // [255][130] halves
    __shared__ float xxs[NSEQ], yys[NSEQ];

    const int b = blockIdx.x, tid = threadIdx.x;
    const int w = tid >> 5, lane = tid & 31;
    const int qr = lane >> 2, qc = lane & 3;
    const int m0 = (w & 1) * 64, n0 = (w >> 1) * 32;

    // ---- stage X, Y (coalesced float4, conflict-free smem stores) ----
    const float4* x4 = (const float4*)(X + (size_t)b * NSEQ * DDIM);
    const float4* y4 = (const float4*)(Y + (size_t)b * NSEQ * DDIM);
    #pragma unroll
    for (int s = 0; s < 16; s++) {
        int idx = s * 256 + tid;            // 0..4095 float4s
        int r = idx >> 5, c4 = (idx & 31) << 2;
        *(float4*)&Xs[r * P + c4] = x4[idx];
        *(float4*)&Ys[r * P + c4] = y4[idx];
    }
    __syncthreads();

    // ---- fp32 norms (t<128 -> xx[t], t>=128 -> yy[t-128]) ----
    {
        int r = tid & 127;
        const float* src = (tid < NSEQ) ? Xs : Ys;
        float s = 0.f;
        #pragma unroll
        for (int c = 0; c < DDIM; c += 4) {
            float4 v = *(const float4*)&src[r * P + c];
            s = fmaf(v.x, v.x, fmaf(v.y, v.y, fmaf(v.z, v.z, fmaf(v.w, v.w, s))));
        }
        if (tid < NSEQ) xxs[r] = s; else yys[r] = s;
    }

    // ---- tf32 HMMA mainloop: 16 K-steps x (4 m-tiles x 4 n-tiles) ----
    float acc[4][4][4];
    #pragma unroll
    for (int mt = 0; mt < 4; mt++)
        #pragma unroll
        for (int nt = 0; nt < 4; nt++)
            #pragma unroll
            for (int r = 0; r < 4; r++) acc[mt][nt][r] = 0.f;

    #pragma unroll 1
    for (int k0 = 0; k0 < DDIM; k0 += 8) {
        uint32_t aF[4][4], bF[4][2];
        #pragma unroll
        for (int mt = 0; mt < 4; mt++) {
            const float* ab = &Xs[(m0 + mt * 16 + qr) * P + k0 + qc];
            aF[mt][0] = f2tf32(ab[0]);
            aF[mt][1] = f2tf32(ab[8 * P]);
            aF[mt][2] = f2tf32(ab[4]);
            aF[mt][3] = f2tf32(ab[8 * P + 4]);
        }
        #pragma unroll
        for (int nt = 0; nt < 4; nt++) {
            const float* bb = &Ys[(n0 + nt * 8 + qr) * P + k0 + qc];
            bF[nt][0] = f2tf32(bb[0]);
            bF[nt][1] = f2tf32(bb[4]);
        }
        #pragma unroll
        for (int mt = 0; mt < 4; mt++)
            #pragma unroll
            for (int nt = 0; nt < 4; nt++)
                mma_tf32(acc[mt][nt], aF[mt], bF[nt]);
    }
    __syncthreads();   // xxs/yys visible; Xs/Ys no longer needed

    // ---- epilogue: D = xx + yy - 2*xy as fp16, scattered diag-major ----
    #pragma unroll
    for (int mt = 0; mt < 4; mt++) {
        int i0 = m0 + mt * 16 + qr;
        float xv0 = xxs[i0], xv1 = xxs[i0 + 8];
        #pragma unroll
        for (int nt = 0; nt < 4; nt++) {
            int j0 = n0 + nt * 8 + 2 * qc;
            float yv0 = yys[j0], yv1 = yys[j0 + 1];
            const float* c = acc[mt][nt];
            Dd[(i0 + j0)     * DP_H + j0]     = __float2half(xv0 + yv0 - 2.f * c[0]);
            Dd[(i0 + j0 + 1) * DP_H + j0 + 1] = __float2half(xv0 + yv1 - 2.f * c[1]);
            Dd[(i0 + 8 + j0)     * DP_H + j0]     = __float2half(xv1 + yv0 - 2.f * c[2]);
            Dd[(i0 + 8 + j0 + 1) * DP_H + j0 + 1] = __float2half(xv1 + yv1 - 2.f * c[3]);
        }
    }
    __syncthreads();

    // ---- coalesced copy: smem diag buffer (pitch 65 words) -> dense gmem ----
    uint32_t* dst = (uint32_t*)(g_Dh + (size_t)b * NDIAG * NSEQ);
    const uint32_t* srcw = (const uint32_t*)Dd;
    for (int v = tid; v < NDIAG * (NSEQ / 2); v += 256) {
        int k = v >> 6, jj = v & 63;
        dst[v] = srcw[k * 65 + jj];
    }
}

// ============================================================================
// Kernel B: soft-DTW DP, one WARP per batch, no block barriers.
// Thread l owns rows 4l..4l+3; boundary values cross lanes via shfl_up.
// D (fp16, diag-major) prefetched 8 diagonals ahead, coalesced 8B/lane.
// Softmin = exact min + rarely-taken logsumexp correction.
// ============================================================================
__global__ __launch_bounds__(128) void dtw_kernel() {
    const int wid = threadIdx.x >> 5, l = threadIdx.x & 31;
    const int b = blockIdx.x * 4 + wid;
    const uint2* Dd2 = (const uint2*)(g_Dh + (size_t)b * NDIAG * NSEQ);

    float km1[4], km2[4];
    #pragma unroll
    for (int r = 0; r < 4; r++) { km1[r] = BIGF; km2[r] = BIGF; }

    uint2 buf[8];
    #pragma unroll
    for (int k = 0; k < 8; k++) buf[k] = Dd2[k * 32 + l];

    for (int kk = 0; kk < 256; kk += 8) {
        #pragma unroll
        for (int u = 0; u < 8; u++) {
            const int k = kk + u;
            uint2 raw = buf[u];
            if (k < NDIAG - 8) buf[u] = Dd2[(k + 8) * 32 + l];   // prefetch
            if (k < NDIAG) {
                float2 f01 = __half22float2(*(__half2*)&raw.x);
                float2 f23 = __half22float2(*(__half2*)&raw.y);
                float dv[4] = {f01.x, f01.y, f23.x, f23.y};
                float up_b = __shfl_up_sync(0xffffffffu, km1[3], 1);
                float dg_b = __shfl_up_sync(0xffffffffu, km2[3], 1);
                if (l == 0) { up_b = BIGF; dg_b = BIGF; }
                float nw[4];
                #pragma unroll
                for (int r = 0; r < 4; r++) {
                    int i = 4 * l + r;
                    int j = k - i;
                    bool valid = (j >= 0) && (j < NSEQ);
                    float up   = (r == 0) ? up_b : km1[r - 1];
                    float left = km1[r];
                    float diag = (r == 0) ? dg_b : km2[r - 1];
                    if (i == 0 && j == 0) diag = 0.0f;
                    float l1 = fminf(diag, up), h1 = fmaxf(diag, up);
                    float m  = fminf(l1, left);
                    float m2 = fminf(h1, fmaxf(l1, left));
                    float rr = dv[r] + m;
                    if (valid && (m2 - m < 0.05f)) {   // rare slow path
                        float s = __expf((m - diag) * 1000.0f)
                                + __expf((m - up)   * 1000.0f)
                                + __expf((m - left) * 1000.0f);
                        rr = dv[r] + m - GAMMA_F * __logf(s);
                    }
                    nw[r] = valid ? rr : BIGF;
                }
                #pragma unroll
                for (int r = 0; r < 4; r++) { km2[r] = km1[r]; km1[r] = nw[r]; }
            }
        }
    }
    if (l == 31) g_dtw[b] = km1[3];   // R[127][127] from k = 254
}

// ============================================================================
// Kernel C: mean over batch, final scalars. d_xx = d_yy = 0 in fp32 (gamma=1e-3:
// soft-DTW of a self-distance matrix reduces to its ~0 diagonal sum).
// ============================================================================
__global__ void finalize_kernel(float* __restrict__ out) {
    __shared__ float ss[16];
    int t = threadIdx.x;
    float v = g_dtw[t];
    #pragma unroll
    for (int o = 16; o > 0; o >>= 1) v += __shfl_down_sync(0xffffffffu, v, o);
    if ((t & 31) == 0) ss[t >> 5] = v;
    __syncthreads();
    if (t < 32) {
        float w = (t < 16) ? ss[t] : 0.0f;
        #pragma unroll
        for (int o = 8; o > 0; o >>= 1) w += __shfl_down_sync(0xffffffffu, w, o);
        if (t == 0) {
            float E = w * (1.0f / (float)BATCH);
            out[0] = E;
            out[1] = 10.0f * sqrtf(E + 1e-10f);
        }
    }
}

extern "C" void kernel_launch(void* const* d_in, const int* in_sizes, int n_in,
                              void* d_out, int out_size) {
    const float* X = (const float*)d_in[0];   // outputs
    const float* Y = (const float*)d_in[1];   // targets
    float* out = (float*)d_out;

    cudaFuncSetAttribute(mma_cost_kernel, cudaFuncAttributeMaxDynamicSharedMemorySize,
                         SM_DYN_BYTES);

    mma_cost_kernel<<<BATCH, 256, SM_DYN_BYTES>>>(X, Y);
    dtw_kernel<<<BATCH / 4, 128>>>();
    finalize_kernel<<<1, BATCH>>>(out);
}

// round 6
// speedup vs baseline: 3.2544x; 3.2544x over previous
#include <cuda_runtime.h>
#include <cuda_fp16.h>
#include <cstdint>
#include <math.h>

#define BATCH 512
#define NSEQ  128
#define DDIM  128
#define GAMMA_F 0.001f
#define BIGF 1e30f

#define NDIAG 255          // 2*NSEQ-1
#define P2    68           // fp32 staging pitch (floats); 68 mod 32 = 4 -> conflict-free frags
#define DP_H  132          // diag buffer pitch in halves (264 B/row: 8B-aligned for uint2)

// Dynamic smem: max(staging 2*128*68*4 = 69632 B, diag 255*132*2 = 67320 B)
#define SM_DYN_BYTES (2 * NSEQ * P2 * 4)

__device__ float g_dtw[BATCH];

__device__ __forceinline__ uint32_t f2tf32(float v) {
    uint32_t r;
    asm("cvt.rna.tf32.f32 %0, %1;" : "=r"(r) : "f"(v));
    return r;
}
__device__ __forceinline__ void mma_tf32(float c[4], const uint32_t a[4],
                                         const uint32_t b[2]) {
    asm volatile(
        "mma.sync.aligned.m16n8k8.row.col.f32.tf32.tf32.f32 "
        "{%0,%1,%2,%3}, {%4,%5,%6,%7}, {%8,%9}, {%0,%1,%2,%3};\n"
        : "+f"(c[0]), "+f"(c[1]), "+f"(c[2]), "+f"(c[3])
        : "r"(a[0]), "r"(a[1]), "r"(a[2]), "r"(a[3]), "r"(b[0]), "r"(b[1]));
}

// ============================================================================
// Fused kernel: per batch b —
//   (1) stage X,Y fp32 into smem in two K-halves (pitch 68, conflict-free)
//   (2) tf32 HMMA gram + fp32 norms (exact), accumulated across both halves
//   (3) epilogue D = xx+yy-2xy -> fp16, scattered DIAG-MAJOR into the SAME
//       smem (staging buffer reused; D never touches gmem)
//   (4) warp 0 runs the soft-DTW DP over smem diagonals, branchless min3
//       (gamma=1e-3: softmin == min to fp32 precision except measure-zero ties)
// 256 threads = 8 warps (2m x 4n), warp tile 64x32, 4x4 m16n8k8 tiles.
// ============================================================================
__global__ __launch_bounds__(256, 2) void fused_kernel(const float* __restrict__ X,
                                                       const float* __restrict__ Y) {
    extern __shared__ float sm[];
    float* Xs = sm;                     // [128][68]
    float* Ys = sm + NSEQ * P2;         // [128][68]
    __shared__ float xxs[NSEQ], yys[NSEQ];

    const int b = blockIdx.x, tid = threadIdx.x;
    const int w = tid >> 5, lane = tid & 31;
    const int qr = lane >> 2, qc = lane & 3;
    const int m0 = (w & 1) * 64, n0 = (w >> 1) * 32;

    float acc[4][4][4];
    #pragma unroll
    for (int mt = 0; mt < 4; mt++)
        #pragma unroll
        for (int nt = 0; nt < 4; nt++)
            #pragma unroll
            for (int r = 0; r < 4; r++) acc[mt][nt][r] = 0.f;

    float nrm = 0.f;   // t<128: xx[t]; t>=128: yy[t-128]

    #pragma unroll
    for (int p = 0; p < 2; p++) {
        // ---- stage K-half p: 2048 float4 per matrix, coalesced ----
        if (p) __syncthreads();          // previous half's reads done
        #pragma unroll
        for (int s = 0; s < 8; s++) {
            int idx = s * 256 + tid;     // 0..2047
            int r = idx >> 4, c4 = (idx & 15) << 2;
            const float4* xg = (const float4*)(X + (size_t)b * NSEQ * DDIM + r * DDIM + p * 64 + c4);
            const float4* yg = (const float4*)(Y + (size_t)b * NSEQ * DDIM + r * DDIM + p * 64 + c4);
            *(float4*)&Xs[r * P2 + c4] = *xg;
            *(float4*)&Ys[r * P2 + c4] = *yg;
        }
        __syncthreads();

        // ---- fp32 norm partials ----
        {
            int r = tid & 127;
            const float* src = (tid < NSEQ) ? Xs : Ys;
            float s = 0.f;
            #pragma unroll
            for (int c = 0; c < 64; c += 4) {
                float4 v = *(const float4*)&src[r * P2 + c];
                s = fmaf(v.x, v.x, fmaf(v.y, v.y, fmaf(v.z, v.z, fmaf(v.w, v.w, s))));
            }
            nrm += s;
        }

        // ---- tf32 HMMA: 8 K-steps on this half ----
        #pragma unroll 1
        for (int k0 = 0; k0 < 64; k0 += 8) {
            uint32_t aF[4][4], bF[4][2];
            #pragma unroll
            for (int mt = 0; mt < 4; mt++) {
                const float* ab = &Xs[(m0 + mt * 16 + qr) * P2 + k0 + qc];
                aF[mt][0] = f2tf32(ab[0]);
                aF[mt][1] = f2tf32(ab[8 * P2]);
                aF[mt][2] = f2tf32(ab[4]);
                aF[mt][3] = f2tf32(ab[8 * P2 + 4]);
            }
            #pragma unroll
            for (int nt = 0; nt < 4; nt++) {
                const float* bb = &Ys[(n0 + nt * 8 + qr) * P2 + k0 + qc];
                bF[nt][0] = f2tf32(bb[0]);
                bF[nt][1] = f2tf32(bb[4]);
            }
            #pragma unroll
            for (int mt = 0; mt < 4; mt++)
                #pragma unroll
                for (int nt = 0; nt < 4; nt++)
                    mma_tf32(acc[mt][nt], aF[mt], bF[nt]);
        }
    }

    if (tid < NSEQ) xxs[tid] = nrm; else yys[tid - NSEQ] = nrm;
    __syncthreads();   // staging reads done; xxs/yys visible; smem free for reuse

    // ---- epilogue: D as fp16, scattered diag-major into reused smem ----
    __half* Dd = (__half*)sm;   // [255][132] halves (67,320 B <= 69,632 B)
    #pragma unroll
    for (int mt = 0; mt < 4; mt++) {
        int i0 = m0 + mt * 16 + qr;
        float xv0 = xxs[i0], xv1 = xxs[i0 + 8];
        #pragma unroll
        for (int nt = 0; nt < 4; nt++) {
            int j0 = n0 + nt * 8 + 2 * qc;
            float yv0 = yys[j0], yv1 = yys[j0 + 1];
            const float* c = acc[mt][nt];
            Dd[(i0 + j0)         * DP_H + j0]     = __float2half(xv0 + yv0 - 2.f * c[0]);
            Dd[(i0 + j0 + 1)     * DP_H + j0 + 1] = __float2half(xv0 + yv1 - 2.f * c[1]);
            Dd[(i0 + 8 + j0)     * DP_H + j0]     = __float2half(xv1 + yv0 - 2.f * c[2]);
            Dd[(i0 + 8 + j0 + 1) * DP_H + j0 + 1] = __float2half(xv1 + yv1 - 2.f * c[3]);
        }
    }
    __syncthreads();

    // ---- soft-DTW DP: warp 0, anti-diagonal wavefront, 4 rows/lane,
    //      branchless min3, boundaries via shfl, D from smem (LDS.64). ----
    if (w == 0) {
        const int l = lane;
        float km1[4], km2[4];
        #pragma unroll
        for (int r = 0; r < 4; r++) { km1[r] = BIGF; km2[r] = BIGF; }

        uint2 cur = *(const uint2*)(Dd + 4 * l);   // diagonal 0
        #pragma unroll 4
        for (int k = 0; k < NDIAG; k++) {
            uint2 nxt = cur;
            if (k < NDIAG - 1) nxt = *(const uint2*)(Dd + (k + 1) * DP_H + 4 * l);
            float2 f01 = __half22float2(*(__half2*)&cur.x);
            float2 f23 = __half22float2(*(__half2*)&cur.y);
            float dv[4] = {f01.x, f01.y, f23.x, f23.y};

            float up_b = __shfl_up_sync(0xffffffffu, km1[3], 1);
            float dg_b = __shfl_up_sync(0xffffffffu, km2[3], 1);
            if (l == 0) { up_b = BIGF; dg_b = BIGF; }

            float nw[4];
            #pragma unroll
            for (int r = 0; r < 4; r++) {
                int i = 4 * l + r;
                int j = k - i;
                bool valid = (j >= 0) && (j < NSEQ);
                float up   = (r == 0) ? up_b : km1[r - 1];
                float left = km1[r];
                float diag = (r == 0) ? dg_b : km2[r - 1];
                if (i == 0 && j == 0) diag = 0.0f;
                float m = fminf(fminf(diag, up), left);
                nw[r] = valid ? dv[r] + m : BIGF;
            }
            #pragma unroll
            for (int r = 0; r < 4; r++) { km2[r] = km1[r]; km1[r] = nw[r]; }
            cur = nxt;
        }
        if (l == 31) g_dtw[b] = km1[3];   // R[127][127] (k = 254)
    }
}

// ============================================================================
// Finalize: mean over batch + scalars. d_xx = d_yy = 0 in fp32 (gamma=1e-3:
// soft-DTW of a self-distance matrix collapses to its ~0 diagonal sum;
// rel impact ~1e-6, validated in R2/R4 at rel_err < 4e-6).
// ============================================================================
__global__ void finalize_kernel(float* __restrict__ out) {
    __shared__ float ss[16];
    int t = threadIdx.x;
    float v = g_dtw[t];
    #pragma unroll
    for (int o = 16; o > 0; o >>= 1) v += __shfl_down_sync(0xffffffffu, v, o);
    if ((t & 31) == 0) ss[t >> 5] = v;
    __syncthreads();
    if (t < 32) {
        float w = (t < 16) ? ss[t] : 0.0f;
        #pragma unroll
        for (int o = 8; o > 0; o >>= 1) w += __shfl_down_sync(0xffffffffu, w, o);
        if (t == 0) {
            float E = w * (1.0f / (float)BATCH);
            out[0] = E;
            out[1] = 10.0f * sqrtf(E + 1e-10f);
        }
    }
}

extern "C" void kernel_launch(void* const* d_in, const int* in_sizes, int n_in,
                              void* d_out, int out_size) {
    const float* X = (const float*)d_in[0];   // outputs
    const float* Y = (const float*)d_in[1];   // targets
    float* out = (float*)d_out;

    cudaFuncSetAttribute(fused_kernel, cudaFuncAttributeMaxDynamicSharedMemorySize,
                         SM_DYN_BYTES);

    fused_kernel<<<BATCH, 256, SM_DYN_BYTES>>>(X, Y);
    finalize_kernel<<<1, BATCH>>>(out);
}

// round 7
// speedup vs baseline: 3.3958x; 1.0434x over previous
#include <cuda_runtime.h>
#include <cuda_fp16.h>
#include <cstdint>
#include <math.h>

#define BATCH 512
#define NSEQ  128
#define DDIM  128
#define GAMMA_F 0.001f
#define BIGF 1e30f

#define NCTA  148
#define NDIAG 255           // 2*NSEQ-1
#define P2    68            // staging pitch (floats); 68 mod 32 = 4 -> conflict-free frags
#define DP_H  132           // diag pitch in halves (264 B: 8B-aligned uint2)
#define BUF_WORDS (2 * NSEQ * P2)              // 17408 floats = 69632 B per buffer
#define SM_DYN_BYTES (3 * BUF_WORDS * 4)       // 208896 B (also >= 255*132*2 per buf)

__device__ float g_dtw[BATCH];
__device__ int   g_ctr = 0;

__device__ __forceinline__ void barsync(int id, int cnt) {
    asm volatile("bar.sync %0, %1;" :: "r"(id), "r"(cnt) : "memory");
}
__device__ __forceinline__ void bararrive(int id, int cnt) {
    asm volatile("bar.arrive %0, %1;" :: "r"(id), "r"(cnt) : "memory");
}
__device__ __forceinline__ float f2tf32f(float v) {
    uint32_t r;
    asm("cvt.rna.tf32.f32 %0, %1;" : "=r"(r) : "f"(v));
    return __uint_as_float(r);
}
__device__ __forceinline__ void mma_tf32(float c[4], const uint32_t a[4],
                                         const uint32_t b[2]) {
    asm volatile(
        "mma.sync.aligned.m16n8k8.row.col.f32.tf32.tf32.f32 "
        "{%0,%1,%2,%3}, {%4,%5,%6,%7}, {%8,%9}, {%0,%1,%2,%3};\n"
        : "+f"(c[0]), "+f"(c[1]), "+f"(c[2]), "+f"(c[3])
        : "r"(a[0]), "r"(a[1]), "r"(a[2]), "r"(a[3]), "r"(b[0]), "r"(b[1]));
}

// Barrier ids: full[p] = 1+p, empty[p] = 4+p (p=0..2), MMA-internal = 7, DP pair = 8.
// full[p]:  256 MMA threads arrive, 32 DP threads sync  (count 288)
// empty[p]: 32 DP threads arrive,  256 MMA threads sync (count 288)

__global__ __launch_bounds__(320, 1) void fused_kernel(const float* __restrict__ X,
                                                       const float* __restrict__ Y,
                                                       float* __restrict__ out) {
    extern __shared__ float sm[];
    __shared__ float xxs[NSEQ], yys[NSEQ];

    const int tid = threadIdx.x, w = tid >> 5, lane = tid & 31;
    const int c = blockIdx.x;
    int nb = 0;
    for (int b = c; b < BATCH; b += NCTA) nb++;     // 4 for c<68, else 3

    if (w < 8) {
        // ================= MMA role: threads 0..255 =================
        const int qr = lane >> 2, qc = lane & 3;
        const int m0 = (w & 1) * 64, n0 = (w >> 1) * 32;

        for (int ib = 0; ib < nb; ib++) {
            const int b = c + ib * NCTA;
            const int p = ib % 3;
            float* buf = sm + p * BUF_WORDS;
            float* Xs = buf;
            float* Ys = buf + NSEQ * P2;

            if (ib >= 3) barsync(4 + p, 288);       // wait DP done on this buffer

            float acc[4][4][4];
            #pragma unroll
            for (int mt = 0; mt < 4; mt++)
                #pragma unroll
                for (int nt = 0; nt < 4; nt++)
                    #pragma unroll
                    for (int r = 0; r < 4; r++) acc[mt][nt][r] = 0.f;

            float nrm = 0.f;

            #pragma unroll
            for (int ph = 0; ph < 2; ph++) {
                if (ph) barsync(7, 256);
                // stage K-half ph, converting to tf32 at store time
                #pragma unroll
                for (int s = 0; s < 8; s++) {
                    int idx = s * 256 + tid;        // 0..2047
                    int r = idx >> 4, c4 = (idx & 15) << 2;
                    float4 xv = *(const float4*)(X + (size_t)b * NSEQ * DDIM + r * DDIM + ph * 64 + c4);
                    float4 yv = *(const float4*)(Y + (size_t)b * NSEQ * DDIM + r * DDIM + ph * 64 + c4);
                    xv.x = f2tf32f(xv.x); xv.y = f2tf32f(xv.y);
                    xv.z = f2tf32f(xv.z); xv.w = f2tf32f(xv.w);
                    yv.x = f2tf32f(yv.x); yv.y = f2tf32f(yv.y);
                    yv.z = f2tf32f(yv.z); yv.w = f2tf32f(yv.w);
                    *(float4*)&Xs[r * P2 + c4] = xv;
                    *(float4*)&Ys[r * P2 + c4] = yv;
                }
                barsync(7, 256);

                // norm partials on tf32-rounded values
                {
                    int r = tid & 127;
                    const float* src = (tid < NSEQ) ? Xs : Ys;
                    float s = 0.f;
                    #pragma unroll
                    for (int cc = 0; cc < 64; cc += 4) {
                        float4 v = *(const float4*)&src[r * P2 + cc];
                        s = fmaf(v.x, v.x, fmaf(v.y, v.y, fmaf(v.z, v.z, fmaf(v.w, v.w, s))));
                    }
                    nrm += s;
                }

                // HMMA mainloop, fragments already tf32 bits
                #pragma unroll 1
                for (int k0 = 0; k0 < 64; k0 += 8) {
                    uint32_t aF[4][4], bF[4][2];
                    #pragma unroll
                    for (int mt = 0; mt < 4; mt++) {
                        const float* ab = &Xs[(m0 + mt * 16 + qr) * P2 + k0 + qc];
                        aF[mt][0] = __float_as_uint(ab[0]);
                        aF[mt][1] = __float_as_uint(ab[8 * P2]);
                        aF[mt][2] = __float_as_uint(ab[4]);
                        aF[mt][3] = __float_as_uint(ab[8 * P2 + 4]);
                    }
                    #pragma unroll
                    for (int nt = 0; nt < 4; nt++) {
                        const float* bb = &Ys[(n0 + nt * 8 + qr) * P2 + k0 + qc];
                        bF[nt][0] = __float_as_uint(bb[0]);
                        bF[nt][1] = __float_as_uint(bb[4]);
                    }
                    #pragma unroll
                    for (int mt = 0; mt < 4; mt++)
                        #pragma unroll
                        for (int nt = 0; nt < 4; nt++)
                            mma_tf32(acc[mt][nt], aF[mt], bF[nt]);
                }
            }

            if (tid < NSEQ) xxs[tid] = nrm; else yys[tid - NSEQ] = nrm;
            barsync(7, 256);   // staging reads done; norms visible; buf reusable

            // epilogue: D = xx + yy - 2*xy -> fp16, diag-major into buf
            __half* Dd = (__half*)buf;   // [255][132] halves = 67320 B
            #pragma unroll
            for (int mt = 0; mt < 4; mt++) {
                int i0 = m0 + mt * 16 + qr;
                float xv0 = xxs[i0], xv1 = xxs[i0 + 8];
                #pragma unroll
                for (int nt = 0; nt < 4; nt++) {
                    int j0 = n0 + nt * 8 + 2 * qc;
                    float yv0 = yys[j0], yv1 = yys[j0 + 1];
                    const float* cA = acc[mt][nt];
                    Dd[(i0 + j0)         * DP_H + j0]     = __float2half(xv0 + yv0 - 2.f * cA[0]);
                    Dd[(i0 + j0 + 1)     * DP_H + j0 + 1] = __float2half(xv0 + yv1 - 2.f * cA[1]);
                    Dd[(i0 + 8 + j0)     * DP_H + j0]     = __float2half(xv1 + yv0 - 2.f * cA[2]);
                    Dd[(i0 + 8 + j0 + 1) * DP_H + j0 + 1] = __float2half(xv1 + yv1 - 2.f * cA[3]);
                }
            }
            barsync(7, 256);               // epilogue writes complete
            bararrive(1 + p, 288);         // signal full[p] to DP
        }
        // MMA warps exit; their arrivals are already registered.
    } else {
        // ================= DP role: warps 8,9 (threads 256..319) =================
        const int d = w - 8, l = lane;

        for (int ib = d; ib < nb; ib += 2) {
            const int b = c + ib * NCTA;
            const int p = ib % 3;
            const __half* Dd = (const __half*)(sm + p * BUF_WORDS);

            barsync(1 + p, 288);           // wait full[p]

            float km1[4], km2[4];
            #pragma unroll
            for (int r = 0; r < 4; r++) { km1[r] = BIGF; km2[r] = BIGF; }
            float up_prev = BIGF;          // = dg boundary for k=0

            uint2 cur = *(const uint2*)(Dd + 4 * l);
            #pragma unroll 4
            for (int k = 0; k < NDIAG; k++) {
                float up_b = __shfl_up_sync(0xffffffffu, km1[3], 1);
                if (l == 0) up_b = BIGF;
                float dg_b = up_prev;      // lane l-1's km1[3] from step k-1
                up_prev = up_b;

                uint2 nxt = cur;
                if (k < NDIAG - 1) nxt = *(const uint2*)(Dd + (k + 1) * DP_H + 4 * l);
                float2 f01 = __half22float2(*(__half2*)&cur.x);
                float2 f23 = __half22float2(*(__half2*)&cur.y);
                float dv[4] = {f01.x, f01.y, f23.x, f23.y};

                float nw[4];
                #pragma unroll
                for (int r = 0; r < 4; r++) {
                    int i = 4 * l + r;
                    int j = k - i;
                    bool valid = (j >= 0) && (j < NSEQ);
                    float up   = (r == 0) ? up_b : km1[r - 1];
                    float left = km1[r];
                    float diag = (r == 0) ? dg_b : km2[r - 1];
                    if (i == 0 && j == 0) diag = 0.0f;
                    float m = fminf(fminf(diag, up), left);
                    nw[r] = valid ? dv[r] + m : BIGF;
                }
                #pragma unroll
                for (int r = 0; r < 4; r++) { km2[r] = km1[r]; km1[r] = nw[r]; }
                cur = nxt;
            }
            if (l == 31) g_dtw[b] = km1[3];   // R[127][127]

            bararrive(4 + p, 288);            // signal empty[p]
        }

        barsync(8, 64);                        // both DP warps done

        if (tid == 256) {
            __threadfence();
            if (atomicAdd(&g_ctr, 1) == NCTA - 1) {
                __threadfence();
                // deterministic fixed-order reduction of g_dtw[0..511]
                float a0 = 0.f, a1 = 0.f, a2 = 0.f, a3 = 0.f;
                float a4 = 0.f, a5 = 0.f, a6 = 0.f, a7 = 0.f;
                for (int i = 0; i < BATCH; i += 32) {
                    float4 v0 = *(const float4*)&g_dtw[i];
                    float4 v1 = *(const float4*)&g_dtw[i + 4];
                    float4 v2 = *(const float4*)&g_dtw[i + 8];
                    float4 v3 = *(const float4*)&g_dtw[i + 12];
                    float4 v4 = *(const float4*)&g_dtw[i + 16];
                    float4 v5 = *(const float4*)&g_dtw[i + 20];
                    float4 v6 = *(const float4*)&g_dtw[i + 24];
                    float4 v7 = *(const float4*)&g_dtw[i + 28];
                    a0 += (v0.x + v0.y) + (v0.z + v0.w);
                    a1 += (v1.x + v1.y) + (v1.z + v1.w);
                    a2 += (v2.x + v2.y) + (v2.z + v2.w);
                    a3 += (v3.x + v3.y) + (v3.z + v3.w);
                    a4 += (v4.x + v4.y) + (v4.z + v4.w);
                    a5 += (v5.x + v5.y) + (v5.z + v5.w);
                    a6 += (v6.x + v6.y) + (v6.z + v6.w);
                    a7 += (v7.x + v7.y) + (v7.z + v7.w);
                }
                float s = ((a0 + a1) + (a2 + a3)) + ((a4 + a5) + (a6 + a7));
                float E = s * (1.0f / (float)BATCH);
                out[0] = E;
                out[1] = 10.0f * sqrtf(E + 1e-10f);
                g_ctr = 0;   // reset for next graph replay
            }
        }
    }
}

extern "C" void kernel_launch(void* const* d_in, const int* in_sizes, int n_in,
                              void* d_out, int out_size) {
    const float* X = (const float*)d_in[0];   // outputs
    const float* Y = (const float*)d_in[1];   // targets
    float* out = (float*)d_out;

    cudaFuncSetAttribute(fused_kernel, cudaFuncAttributeMaxDynamicSharedMemorySize,
                         SM_DYN_BYTES);

    fused_kernel<<<NCTA, 320, SM_DYN_BYTES>>>(X, Y, out);
}